// round 5
// baseline (speedup 1.0000x reference)
#include <cuda_runtime.h>

// Warper3d: 3D trilinear warp (grid_sample, align_corners=False, border pad).
//   img : [B=4, 1, D=64, H=192, W=192] f32
//   flow: [B=4, 3, D=64, H=192, W=192] f32
//   out : [B=4, 1, D=64, H=192, W=192] f32
//
// R4 ncu: L1tex-bound (81%). Dominant cost = per-gather wavefront replays:
// each lane has an independently jittered (y0,z0) row, ~L≈20-28 distinct
// lines per gather instruction. x0/x1 share a line 31/32 of the time, so
// fusing each row's pair into ONE aligned float4 gather (+ predicated scalar
// fallback for the off==3 quarter) cuts gather wavefronts 8L -> ~5L.

#define BB 4
#define DD 64
#define HH 192
#define WW 192
#define SP (DD * HH * WW)

#define TX 64
#define TY 2
#define TZ 2

// One row's (v[x0], v[x1]) via a single aligned float4 + rare fallback.
// row is 16B-aligned (row pitch 192 floats = 768B). a = x0&~3 in [0,188].
__device__ __forceinline__ float2 gather_pair(const float* __restrict__ row,
                                              int x0, int x1)
{
    int a   = x0 & ~3;
    int off = x0 & 3;
    float4 f = __ldg((const float4*)(row + a));
    float v0 = (off == 0) ? f.x : (off == 1) ? f.y : (off == 2) ? f.z : f.w;
    float v1;
    if (off == 3)  v1 = __ldg(row + x1);     // 25% of lanes; x0==191 -> x1==191 == v0
    else           v1 = (off == 0) ? f.y : (off == 1) ? f.z : f.w;
    return make_float2(v0, v1);
}

__global__ __launch_bounds__(TX * TY * TZ)
void warp3d_kernel(const float* __restrict__ img,
                   const float* __restrict__ flow,
                   float* __restrict__ out)
{
    int x = blockIdx.x * TX + threadIdx.x;
    int y = blockIdx.y * TY + threadIdx.y;
    int zb = blockIdx.z;                    // [0,128): z-tile (32) x batch (4)
    int z = (zb & 31) * TZ + threadIdx.z;
    int b = zb >> 5;

    int s = (z * HH + y) * WW + x;

    const float* fb = flow + (size_t)b * 3 * SP;
    float fx = __ldcs(fb + s);
    float fy = __ldcs(fb + SP + s);
    float fz = __ldcs(fb + 2 * SP + s);

    // Reference composition gx=2v/(S-1)-1; ix=((gx+1)*S-1)/2 == v*S/(S-1)-0.5
    const float KX = (float)WW / (float)(WW - 1);
    const float KY = (float)HH / (float)(HH - 1);
    const float KZ = (float)DD / (float)(DD - 1);

    float ix = fmaf((float)x + fx, KX, -0.5f);
    float iy = fmaf((float)y + fy, KY, -0.5f);
    float iz = fmaf((float)z + fz, KZ, -0.5f);
    ix = fminf(fmaxf(ix, 0.0f), (float)(WW - 1));
    iy = fminf(fmaxf(iy, 0.0f), (float)(HH - 1));
    iz = fminf(fmaxf(iz, 0.0f), (float)(DD - 1));

    float x0f = floorf(ix); float wx = ix - x0f;
    float y0f = floorf(iy); float wy = iy - y0f;
    float z0f = floorf(iz); float wz = iz - z0f;

    int x0 = (int)x0f; int x1 = min(x0 + 1, WW - 1);
    int y0 = (int)y0f; int y1 = min(y0 + 1, HH - 1);
    int z0 = (int)z0f; int z1 = min(z0 + 1, DD - 1);

    const float* ib = img + (size_t)b * SP;
    const float* p00 = ib + (z0 * HH + y0) * WW;
    const float* p01 = ib + (z0 * HH + y1) * WW;
    const float* p10 = ib + (z1 * HH + y0) * WW;
    const float* p11 = ib + (z1 * HH + y1) * WW;

    float2 g00 = gather_pair(p00, x0, x1);   // (v000, v001)
    float2 g01 = gather_pair(p01, x0, x1);   // (v010, v011)
    float2 g10 = gather_pair(p10, x0, x1);   // (v100, v101)
    float2 g11 = gather_pair(p11, x0, x1);   // (v110, v111)

    float c00 = fmaf(wx, g00.y - g00.x, g00.x);
    float c01 = fmaf(wx, g01.y - g01.x, g01.x);
    float c10 = fmaf(wx, g10.y - g10.x, g10.x);
    float c11 = fmaf(wx, g11.y - g11.x, g11.x);
    float c0  = fmaf(wy, c01 - c00, c00);
    float c1  = fmaf(wy, c11 - c10, c10);
    float r   = fmaf(wz, c1 - c0, c0);

    __stcs(out + (size_t)b * SP + s, r);
}

extern "C" void kernel_launch(void* const* d_in, const int* in_sizes, int n_in,
                              void* d_out, int out_size)
{
    const float* img  = (const float*)d_in[0];
    const float* flow = (const float*)d_in[1];
    float* out = (float*)d_out;

    dim3 block(TX, TY, TZ);                       // 256 threads
    dim3 grid(WW / TX, HH / TY, (DD / TZ) * BB);  // 3 x 96 x 128
    warp3d_kernel<<<grid, block>>>(img, flow, out);
}

// round 6
// speedup vs baseline: 1.4576x; 1.4576x over previous
#include <cuda_runtime.h>

// Warper3d: 3D trilinear warp (grid_sample, align_corners=False, border pad).
//   img : [B=4, 1, D=64, H=192, W=192] f32
//   flow: [B=4, 3, D=64, H=192, W=192] f32
//   out : [B=4, 1, D=64, H=192, W=192] f32
//
// Model (R3-R5 evidence): kernel is L1tex-wavefront bound on the 8 scalar
// gathers (random per-voxel rows => ~8 distinct sectors/gather-instr; 4B
// lanes already fit the 32B sector return width, so scalar gathers are at
// the per-sector byte floor; wide gathers REGRESS). This version keeps R4's
// scalar gathers and attacks the remaining issue/latency slack: 2 x-adjacent
// voxels per thread, 16 independent gather LDGs in flight, float2 streams.

#define BB 4
#define DD 64
#define HH 192
#define WW 192
#define SP (DD * HH * WW)

#define TX 48      // threads in x; each thread does 2 consecutive x voxels
#define TY 2
#define TZ 2

__global__ __launch_bounds__(TX * TY * TZ)
void warp3d_kernel(const float* __restrict__ img,
                   const float* __restrict__ flow,
                   float* __restrict__ out)
{
    int xp = (blockIdx.x * TX + threadIdx.x) * 2;      // even; covers xp, xp+1
    int y  = blockIdx.y * TY + threadIdx.y;
    int zb = blockIdx.z;                               // z-tile (32) x batch (4)
    int z  = (zb & 31) * TZ + threadIdx.z;
    int b  = zb >> 5;

    int s = (z * HH + y) * WW + xp;                    // even => 8B aligned

    const float* fb = flow + (size_t)b * 3 * SP;
    float2 fx = __ldg((const float2*)(fb + s));
    float2 fy = __ldg((const float2*)(fb + SP + s));
    float2 fz = __ldg((const float2*)(fb + 2 * SP + s));

    // Reference composition gx=2v/(S-1)-1; ix=((gx+1)*S-1)/2 == v*S/(S-1)-0.5
    const float KX = (float)WW / (float)(WW - 1);
    const float KY = (float)HH / (float)(HH - 1);
    const float KZ = (float)DD / (float)(DD - 1);

    const float* ib = img + (size_t)b * SP;

    float res[2];
    const float fxa[2] = {fx.x, fx.y};
    const float fya[2] = {fy.x, fy.y};
    const float fza[2] = {fz.x, fz.y};

    #pragma unroll
    for (int k = 0; k < 2; k++) {
        float ix = fmaf((float)(xp + k) + fxa[k], KX, -0.5f);
        float iy = fmaf((float)y + fya[k],        KY, -0.5f);
        float iz = fmaf((float)z + fza[k],        KZ, -0.5f);
        ix = fminf(fmaxf(ix, 0.0f), (float)(WW - 1));
        iy = fminf(fmaxf(iy, 0.0f), (float)(HH - 1));
        iz = fminf(fmaxf(iz, 0.0f), (float)(DD - 1));

        float x0f = floorf(ix); float wx = ix - x0f;
        float y0f = floorf(iy); float wy = iy - y0f;
        float z0f = floorf(iz); float wz = iz - z0f;

        int x0 = (int)x0f; int x1 = min(x0 + 1, WW - 1);
        int y0 = (int)y0f; int y1 = min(y0 + 1, HH - 1);
        int z0 = (int)z0f; int z1 = min(z0 + 1, DD - 1);

        const float* p00 = ib + (z0 * HH + y0) * WW;
        const float* p01 = ib + (z0 * HH + y1) * WW;
        const float* p10 = ib + (z1 * HH + y0) * WW;
        const float* p11 = ib + (z1 * HH + y1) * WW;

        float v000 = __ldg(p00 + x0);
        float v001 = __ldg(p00 + x1);
        float v010 = __ldg(p01 + x0);
        float v011 = __ldg(p01 + x1);
        float v100 = __ldg(p10 + x0);
        float v101 = __ldg(p10 + x1);
        float v110 = __ldg(p11 + x0);
        float v111 = __ldg(p11 + x1);

        float c00 = fmaf(wx, v001 - v000, v000);
        float c01 = fmaf(wx, v011 - v010, v010);
        float c10 = fmaf(wx, v101 - v100, v100);
        float c11 = fmaf(wx, v111 - v110, v110);
        float c0  = fmaf(wy, c01 - c00, c00);
        float c1  = fmaf(wy, c11 - c10, c10);
        res[k]    = fmaf(wz, c1 - c0, c0);
    }

    *(float2*)(out + (size_t)b * SP + s) = make_float2(res[0], res[1]);
}

extern "C" void kernel_launch(void* const* d_in, const int* in_sizes, int n_in,
                              void* d_out, int out_size)
{
    const float* img  = (const float*)d_in[0];
    const float* flow = (const float*)d_in[1];
    float* out = (float*)d_out;

    dim3 block(TX, TY, TZ);                        // 192 threads
    dim3 grid(WW / (TX * 2), HH / TY, (DD / TZ) * BB);  // 2 x 96 x 128
    warp3d_kernel<<<grid, block>>>(img, flow, out);
}